// round 12
// baseline (speedup 1.0000x reference)
#include <cuda_runtime.h>
#include <cuda_bf16.h>
#include <cstdint>

// ---------------------------------------------------------------------------
// GATModel on GB300: tcgen05 bf16 split-GEMM, full row-stripe per CTA
// (C[128,256] in TMEM, A staged once, B L2-resident) + two-phase GAT agg.
// R12: kill the 4x A re-read seen in R11's profile (L2=57.7%, tensor=8.7%).
// ---------------------------------------------------------------------------

#if defined(__CUDA_ARCH_FEAT_SM103_ALL) || defined(__CUDA_ARCH_FEAT_SM100_ALL) || \
    defined(__CUDA_ARCH_FEAT_SM101_ALL) || defined(__CUDA_ARCH_SPECIFIC__)
#define TC_OK 1
#else
#define TC_OK 0
#endif

#define NMAX 50000
#define EMAX 500000

__device__ float          g_buf1[NMAX * 256];
__device__ __nv_bfloat16  g_a_hi[NMAX * 256];
__device__ __nv_bfloat16  g_a_lo[NMAX * 256];
__device__ __nv_bfloat16  g_wb_hi[256 * 256];
__device__ __nv_bfloat16  g_wb_lo[256 * 256];
__device__ float g_ssrc[NMAX * 4];
__device__ float g_sdst[NMAX * 4];
__device__ int   g_counts[NMAX];
__device__ int   g_rowbeg[NMAX];
__device__ int   g_rowend[NMAX];
__device__ int   g_cursor[NMAX];
__device__ int   g_csrc[EMAX];
__device__ int   g_is64;
__device__ int   g_total;

// ---------------- edge_index dtype detection ----------------
__global__ void detect_dtype(const void* __restrict__ ei, int N) {
    const long long* p = (const long long*)ei;
    int ok = 1;
    for (int i = 0; i < 16; i++) {
        long long v = p[i];
        if (v < 0 || v >= (long long)N) ok = 0;
    }
    g_is64 = ok;
}
__device__ __forceinline__ int load_idx(const void* ei, long long pos) {
    if (g_is64) return (int)((const long long*)ei)[pos];
    return ((const int*)ei)[pos];
}

// ---------------- CSR build ----------------
__global__ void zero_counts(int N) {
    int i = blockIdx.x * blockDim.x + threadIdx.x;
    if (i < N) g_counts[i] = 0;
    if (i == 0) g_total = 0;
}
__global__ void hist_kernel(const void* __restrict__ ei, int E, int N) {
    int e = blockIdx.x * blockDim.x + threadIdx.x;
    if (e < E) {
        int d = load_idx(ei, (long long)E + e);
        if (d >= 0 && d < N) atomicAdd(&g_counts[d], 1);
    }
}
__global__ void __launch_bounds__(1024)
alloc_rows(int N) {
    __shared__ int sh[1024];
    __shared__ int sbase;
    int tid = threadIdx.x;
    int i = blockIdx.x * 1024 + tid;
    int c = (i < N) ? g_counts[i] : 0;
    sh[tid] = c;
    __syncthreads();
    for (int off = 1; off < 1024; off <<= 1) {
        int v = (tid >= off) ? sh[tid - off] : 0;
        __syncthreads();
        sh[tid] += v;
        __syncthreads();
    }
    if (tid == 1023) sbase = atomicAdd(&g_total, sh[1023]);
    __syncthreads();
    if (i < N) {
        int b = sbase + sh[tid] - c;
        g_rowbeg[i] = b;
        g_rowend[i] = b + c;
        g_cursor[i] = b;
    }
}
__global__ void scatter_kernel(const void* __restrict__ ei, int E, int N) {
    int e = blockIdx.x * blockDim.x + threadIdx.x;
    if (e < E) {
        int d = load_idx(ei, (long long)E + e);
        int s = load_idx(ei, e);
        if (d >= 0 && d < N && s >= 0 && s < N) {
            int pos = atomicAdd(&g_cursor[d], 1);
            if (pos >= 0 && pos < E) g_csrc[pos] = s;
        }
    }
}

// ---------------- fp32 -> bf16 hi/lo split conversions ----------------
__global__ void conv_split_x(const float* __restrict__ src, int n2) {
    int i = blockIdx.x * blockDim.x + threadIdx.x;
    if (i < n2) {
        float2 v = ((const float2*)src)[i];
        __nv_bfloat16 h0 = __float2bfloat16(v.x);
        __nv_bfloat16 h1 = __float2bfloat16(v.y);
        ((__nv_bfloat162*)g_a_hi)[i] = __halves2bfloat162(h0, h1);
        ((__nv_bfloat162*)g_a_lo)[i] = __halves2bfloat162(
            __float2bfloat16(v.x - __bfloat162float(h0)),
            __float2bfloat16(v.y - __bfloat162float(h1)));
    }
}
__global__ void conv_split_w(const float* __restrict__ src, int n2) {
    int i = blockIdx.x * blockDim.x + threadIdx.x;
    if (i < n2) {
        float2 v = ((const float2*)src)[i];
        __nv_bfloat16 h0 = __float2bfloat16(v.x);
        __nv_bfloat16 h1 = __float2bfloat16(v.y);
        ((__nv_bfloat162*)g_wb_hi)[i] = __halves2bfloat162(h0, h1);
        ((__nv_bfloat162*)g_wb_lo)[i] = __halves2bfloat162(
            __float2bfloat16(v.x - __bfloat162float(h0)),
            __float2bfloat16(v.y - __bfloat162float(h1)));
    }
}

// ---------------- tcgen05 helpers (arch-specific pass only) ----------------
#if TC_OK
__device__ __forceinline__ uint32_t elect_one_pred() {
    uint32_t pred;
    asm volatile("{\n\t.reg .pred p;\n\telect.sync _|p, 0xFFFFFFFF;\n\t"
                 "selp.b32 %0, 1, 0, p;\n\t}" : "=r"(pred));
    return pred;
}
__device__ __forceinline__ uint32_t smem_to_u32(const void* p) {
    uint32_t a;
    asm("{ .reg .u64 t; cvta.to.shared.u64 t, %1; cvt.u32.u64 %0, t; }"
        : "=r"(a) : "l"(p));
    return a;
}
#define MBARRIER_INIT(mbar, count) \
    asm volatile("mbarrier.init.shared.b64 [%0], %1;" \
                 :: "r"((uint32_t)(mbar)), "r"((uint32_t)(count)) : "memory")
#define MBARRIER_WAIT_PARITY(mbar, parity) do { \
    uint32_t _m = (uint32_t)(mbar), _p = (uint32_t)(parity), _d; \
    asm volatile("{\n\t.reg .pred p;\n\t" \
        "mbarrier.try_wait.parity.acquire.cta.shared::cta.b64 p, [%1], %2;\n\t" \
        "selp.b32 %0, 1, 0, p;\n\t}" : "=r"(_d) : "r"(_m), "r"(_p) : "memory"); \
    if (!_d) { \
        asm volatile("{\n\t.reg .pred P1;\n\t" \
            "WL_%=:\n\t" \
            "mbarrier.try_wait.parity.acquire.cta.shared::cta.b64 P1, [%0], %1, 0x989680;\n\t" \
            "@P1 bra.uni WD_%=;\n\tbra.uni WL_%=;\n\tWD_%=:\n\t}" \
            :: "r"(_m), "r"(_p) : "memory"); \
    } \
} while (0)
#define TCGEN05_ALLOC(sr, n) \
    asm volatile("tcgen05.alloc.cta_group::1.sync.aligned.shared::cta.b32 [%0], %1;" \
                 :: "r"((uint32_t)(sr)), "r"((uint32_t)(n)) : "memory")
#define TCGEN05_DEALLOC(t, n) \
    asm volatile("tcgen05.dealloc.cta_group::1.sync.aligned.b32 %0, %1;" \
                 :: "r"(t), "r"((uint32_t)(n)))
#define TCGEN05_RELINQ() \
    asm volatile("tcgen05.relinquish_alloc_permit.cta_group::1.sync.aligned;")
#define TCGEN05_COMMIT(mbar) \
    asm volatile("tcgen05.commit.cta_group::1.mbarrier::arrive::one.shared::cluster.b64 [%0];" \
                 :: "r"((uint32_t)(mbar)) : "memory")
#define TCGEN05_FENCE_AFTER() \
    asm volatile("tcgen05.fence::after_thread_sync;" ::: "memory")
#define TCGEN05_WAIT_LD() \
    asm volatile("tcgen05.wait::ld.sync.aligned;" ::: "memory")
#define TCGEN05_LD_32X32B_X32(r, ta) \
    asm volatile("tcgen05.ld.sync.aligned.32x32b.x32.b32 " \
        "{%0, %1, %2, %3, %4, %5, %6, %7, %8, %9, %10, %11, %12, %13, %14, %15, " \
        " %16, %17, %18, %19, %20, %21, %22, %23, %24, %25, %26, %27, %28, %29, %30, %31}, [%32];" \
        : "=r"((r)[0]), "=r"((r)[1]), "=r"((r)[2]), "=r"((r)[3]), \
          "=r"((r)[4]), "=r"((r)[5]), "=r"((r)[6]), "=r"((r)[7]), \
          "=r"((r)[8]), "=r"((r)[9]), "=r"((r)[10]), "=r"((r)[11]), \
          "=r"((r)[12]), "=r"((r)[13]), "=r"((r)[14]), "=r"((r)[15]), \
          "=r"((r)[16]), "=r"((r)[17]), "=r"((r)[18]), "=r"((r)[19]), \
          "=r"((r)[20]), "=r"((r)[21]), "=r"((r)[22]), "=r"((r)[23]), \
          "=r"((r)[24]), "=r"((r)[25]), "=r"((r)[26]), "=r"((r)[27]), \
          "=r"((r)[28]), "=r"((r)[29]), "=r"((r)[30]), "=r"((r)[31]) \
        : "r"(ta))
#define CP_ASYNC16(dst, src) \
    asm volatile("cp.async.cg.shared.global [%0], [%1], 16;" \
                 :: "r"((uint32_t)(dst)), "l"(src) : "memory")
#define CP_COMMIT() \
    asm volatile("cp.async.commit_group;" ::: "memory")
#define CP_WAIT_GROUP(n) \
    asm volatile("cp.async.wait_group %0;" :: "n"(n) : "memory")

__device__ __forceinline__ uint64_t make_desc(uint32_t addr) {
    uint64_t base = (uint64_t(2) << 61) | (uint64_t(1) << 46) |
                    (uint64_t(64) << 32) | (uint64_t(1) << 16);
    return base | ((uint64_t)(addr >> 4) & 0x3FFF);
}
__device__ __forceinline__ void mma_f16_ss(uint32_t d, uint64_t ad, uint64_t bd,
                                           uint32_t idesc, bool en) {
    uint32_t e = en ? 1u : 0u;
    asm volatile("{\n\t.reg .pred p;\n\tsetp.ne.u32 p, %5, 0;\n\t"
                 "tcgen05.mma.cta_group::1.kind::f16 [%0], %1, %2, %3, {%4, %4, %4, %4}, p;\n\t}"
                 :: "r"(d), "l"(ad), "l"(bd), "r"(idesc), "r"(0u), "r"(e)
                 : "memory");
}
#define MMA_IDESC 0x8100490u
#endif  // TC_OK

// ---------------- tcgen05 split-GEMM: full row-stripe per CTA ----------------
// C[128, Nout] per CTA. K in 4 stages of 64, double-buffered.
// Stage: A_hi 16K | A_lo 16K | B_hi 32K (256 rows) | B_lo 32K = 96K. 2 bufs.
#define SM_TMEM 0
#define SM_MB0 8
#define SM_MB1 16
#define SM_BUF 1024
#define STG_SZ 98304
#define OFF_ALO 16384
#define OFF_BHI 32768
#define OFF_BLO 65536
#define SM_TOTAL (1024 + 2 * STG_SZ)

__global__ void __launch_bounds__(256)
gemm_tc(const float* __restrict__ bias,
        float* __restrict__ Cext, int toExt, int M, int Nout,
        const float* __restrict__ a_src, const float* __restrict__ a_dst) {
#if TC_OK
    extern __shared__ char smem[];
    uint32_t sb = smem_to_u32(smem);
    int tid = threadIdx.x;
    int wid = tid >> 5;
    int lane = tid & 31;
    int row0 = blockIdx.x * 128;
    int nCB = Nout >> 6;
    float* C = toExt ? Cext : (float*)g_buf1;

    if (wid == 0) {
        TCGEN05_ALLOC(sb + SM_TMEM, 256);
        TCGEN05_RELINQ();
    }
    if (tid == 0) {
        MBARRIER_INIT(sb + SM_MB0, 1);
        MBARRIER_INIT(sb + SM_MB1, 1);
    }
    __syncthreads();
    uint32_t tmem;
    asm volatile("ld.shared.b32 %0, [%1];" : "=r"(tmem) : "r"(sb + SM_TMEM));

    // ---- per-thread load mappings ----
    int ar = tid & 127;
    bool a_hi = tid < 128;
    const __nv_bfloat16* a_srcp =
        (a_hi ? g_a_hi : g_a_lo) + (size_t)(row0 + ar) * 256;
    int a_off_base = (ar >> 3) * 1024 + (ar & 7) * 128;
    int a_sub = a_hi ? 0 : OFF_ALO;
    bool a_ok = (row0 + ar) < M;

    int br = tid;                        // B row 0..255 (both dtypes)
    bool b_ok = br < Nout;
    const __nv_bfloat16* b_hi_p = g_wb_hi + (size_t)br * 256;
    const __nv_bfloat16* b_lo_p = g_wb_lo + (size_t)br * 256;
    int b_off_base = (br >> 3) * 1024 + (br & 7) * 128;

    auto load_stage = [&](int s) {
        uint32_t bufb = sb + SM_BUF + (s & 1) * STG_SZ;
        {   // A: 8 uint4 (this row's 128B slice of stage s)
            const uint4* src = (const uint4*)(a_srcp + s * 64);
#pragma unroll
            for (int c = 0; c < 8; c++) {
                int off = a_off_base + c * 16;
                off ^= (off >> 3) & 0x70;
                if (a_ok) CP_ASYNC16(bufb + a_sub + off, src + c);
                else *(uint4*)(smem + (bufb - sb) + a_sub + off) =
                         make_uint4(0u, 0u, 0u, 0u);
            }
        }
        if (b_ok) {   // B: 8 uint4 per dtype
            const uint4* sh = (const uint4*)(b_hi_p + s * 64);
            const uint4* sl = (const uint4*)(b_lo_p + s * 64);
#pragma unroll
            for (int c = 0; c < 8; c++) {
                int off = b_off_base + c * 16;
                off ^= (off >> 3) & 0x70;
                CP_ASYNC16(bufb + OFF_BHI + off, sh + c);
                CP_ASYNC16(bufb + OFF_BLO + off, sl + c);
            }
        }
        CP_COMMIT();
    };

    load_stage(0);
    load_stage(1);

#pragma unroll
    for (int s = 0; s < 4; s++) {
        if (s < 3) CP_WAIT_GROUP(1); else CP_WAIT_GROUP(0);
        __syncthreads();
        asm volatile("fence.proxy.async.shared::cta;" ::: "memory");

        if (wid == 0) {
            if (elect_one_pred()) {
                uint32_t bufb = sb + SM_BUF + (s & 1) * STG_SZ;
                uint64_t dA_hi = make_desc(bufb);
                uint64_t dA_lo = make_desc(bufb + OFF_ALO);
                uint64_t dB_hi = make_desc(bufb + OFF_BHI);
                uint64_t dB_lo = make_desc(bufb + OFF_BLO);
#pragma unroll
                for (int term = 0; term < 3; term++) {
                    uint64_t da = (term == 2) ? dA_lo : dA_hi;
                    uint64_t db = (term == 1) ? dB_lo : dB_hi;
#pragma unroll
                    for (int kc = 0; kc < 4; kc++) {
                        bool en = !(s == 0 && term == 0 && kc == 0);
                        for (int cb = 0; cb < nCB; cb++) {
                            // cb selects 64 B-rows: +8KB smem = +512 desc units
                            mma_f16_ss(tmem + cb * 64, da + kc * 2,
                                       db + cb * 512 + kc * 2, MMA_IDESC, en);
                        }
                    }
                }
                TCGEN05_COMMIT(sb + ((s & 1) ? SM_MB1 : SM_MB0));
            }
        }
        if (s < 2) {
            MBARRIER_WAIT_PARITY(sb + ((s & 1) ? SM_MB1 : SM_MB0), 0);
            load_stage(s + 2);
        }
    }

    MBARRIER_WAIT_PARITY(sb + SM_MB0, 1);
    MBARRIER_WAIT_PARITY(sb + SM_MB1, 1);
    TCGEN05_FENCE_AFTER();

    // ---- epilogue: each thread owns full row r; per-cb to bound registers ----
    if (wid < 4) {
        int r = row0 + wid * 32 + lane;
        for (int cb = 0; cb < nCB; cb++) {
            uint32_t d0[32], d1[32];
            TCGEN05_LD_32X32B_X32(d0, tmem + cb * 64);
            TCGEN05_LD_32X32B_X32(d1, tmem + cb * 64 + 32);
            TCGEN05_WAIT_LD();
            if (r < M) {
                float cv[64];
#pragma unroll
                for (int j = 0; j < 32; j++) {
                    cv[j] = __uint_as_float(d0[j]);
                    cv[32 + j] = __uint_as_float(d1[j]);
                }
                int c0 = cb * 64;
                if (bias) {
#pragma unroll
                    for (int j = 0; j < 64; j++) cv[j] += bias[c0 + j];
                }
                float* crow = C + (size_t)r * Nout + c0;
#pragma unroll
                for (int q = 0; q < 16; q++) {
                    *(float4*)(crow + q * 4) = make_float4(
                        cv[4 * q], cv[4 * q + 1], cv[4 * q + 2], cv[4 * q + 3]);
                }
                if (a_src) {   // head == cb (Nout=256 path)
                    float vs = 0.f, vd = 0.f;
#pragma unroll
                    for (int j = 0; j < 64; j++) {
                        vs = fmaf(cv[j], a_src[c0 + j], vs);
                        vd = fmaf(cv[j], a_dst[c0 + j], vd);
                    }
                    g_ssrc[r * 4 + cb] = vs;
                    g_sdst[r * 4 + cb] = vd;
                }
            }
        }
    }
    __syncthreads();
    if (tid == 0) {
        asm volatile("mbarrier.inval.shared.b64 [%0];" :: "r"(sb + SM_MB0) : "memory");
        asm volatile("mbarrier.inval.shared.b64 [%0];" :: "r"(sb + SM_MB1) : "memory");
    }
    if (wid == 0) TCGEN05_DEALLOC(tmem, 256);
#endif  // TC_OK
}

// ---------------- GAT aggregate + BN + ELU (chunked two-phase) ----------------
__global__ void __launch_bounds__(128)
gat_agg(const float* __restrict__ gamma, const float* __restrict__ beta,
        const float* __restrict__ mean, const float* __restrict__ var) {
    __shared__ float wgt[32][4];
    __shared__ int   sidx[32];
    __shared__ float smax[4];

    int n = blockIdx.x;
    int tid = threadIdx.x;
    int head = tid >> 5;
    int lane = tid & 31;
    int beg = g_rowbeg[n];
    int end = g_rowend[n];
    const float* hfeat = g_buf1;

    {
        float sd_h = g_sdst[n * 4 + head];
        float m = 0.f;
        for (int i = beg + lane; i < end; i += 32) {
            int s = g_csrc[i];
            float e = g_ssrc[s * 4 + head] + sd_h;
            e = (e >= 0.f) ? e : 0.2f * e;
            m = fmaxf(m, e);
        }
#pragma unroll
        for (int o = 16; o; o >>= 1) m = fmaxf(m, __shfl_xor_sync(~0u, m, o));
        if (lane == 0) smax[head] = m;
    }
    __syncthreads();

    int eh = tid & 3;
    int eo = tid >> 2;
    float sd_eh = g_sdst[n * 4 + eh];
    float m_eh = smax[eh];

    float acc0 = 0.f, acc1 = 0.f, ws = 0.f;
    int c = tid * 2;

    for (int base = beg; base < end; base += 32) {
        int cnt = min(32, end - base);
        {
            float w = 0.f;
            int s = -1;
            if (eo < cnt) {
                s = g_csrc[base + eo];
                float e = g_ssrc[s * 4 + eh] + sd_eh;
                e = (e >= 0.f) ? e : 0.2f * e;
                w = __expf(e - m_eh);
            }
            wgt[eo][eh] = w;
            if (eh == 0) sidx[eo] = s;
        }
        __syncthreads();
        for (int j = 0; j < cnt; j++) {
            float w = wgt[j][head];
            ws += w;
            float2 hv = *(const float2*)&hfeat[(size_t)sidx[j] * 256 + c];
            acc0 = fmaf(w, hv.x, acc0);
            acc1 = fmaf(w, hv.y, acc1);
        }
        __syncthreads();
    }

    float inv = 1.f / fmaxf(ws, 1e-9f);
    float o0 = acc0 * inv;
    float o1 = acc1 * inv;

    o0 = (o0 - mean[c]) * rsqrtf(var[c] + 1e-5f) * gamma[c] + beta[c];
    o1 = (o1 - mean[c + 1]) * rsqrtf(var[c + 1] + 1e-5f) * gamma[c + 1] + beta[c + 1];
    o0 = (o0 > 0.f) ? o0 : expm1f(o0);
    o1 = (o1 > 0.f) ? o1 : expm1f(o1);

    __nv_bfloat16 h0 = __float2bfloat16(o0);
    __nv_bfloat16 h1 = __float2bfloat16(o1);
    size_t idx2 = ((size_t)n * 256 + c) >> 1;
    ((__nv_bfloat162*)g_a_hi)[idx2] = __halves2bfloat162(h0, h1);
    ((__nv_bfloat162*)g_a_lo)[idx2] = __halves2bfloat162(
        __float2bfloat16(o0 - __bfloat162float(h0)),
        __float2bfloat16(o1 - __bfloat162float(h1)));
}

// ---------------------------------------------------------------------------
extern "C" void kernel_launch(void* const* d_in, const int* in_sizes, int n_in,
                              void* d_out, int out_size) {
    const float* x   = (const float*)d_in[0];
    const void*  ei  = d_in[1];
    const float* W1  = (const float*)d_in[2];
    const float* as1 = (const float*)d_in[3];
    const float* ad1 = (const float*)d_in[4];
    const float* g1  = (const float*)d_in[5];
    const float* b1  = (const float*)d_in[6];
    const float* m1  = (const float*)d_in[7];
    const float* v1  = (const float*)d_in[8];
    const float* W2  = (const float*)d_in[9];
    const float* as2 = (const float*)d_in[10];
    const float* ad2 = (const float*)d_in[11];
    const float* g2  = (const float*)d_in[12];
    const float* b2  = (const float*)d_in[13];
    const float* m2  = (const float*)d_in[14];
    const float* v2  = (const float*)d_in[15];
    const float* Wc  = (const float*)d_in[16];
    const float* bc  = (const float*)d_in[17];
    float* out = (float*)d_out;

    int N = in_sizes[0] / 256;
    int E = in_sizes[1] / 2;

    cudaFuncSetAttribute(gemm_tc, cudaFuncAttributeMaxDynamicSharedMemorySize,
                         SM_TOTAL);

    dim3 grid_l((N + 127) / 128);
    int nx2 = N * 128;
    int nw2 = 256 * 256 / 2;
    int nc2 = 64 * 256 / 2;

    // gemm_tc is the 4th launch: ncu captures it.
    conv_split_x<<<(nx2 + 255) / 256, 256>>>(x, nx2);              // 1
    conv_split_w<<<(nw2 + 255) / 256, 256>>>(W1, nw2);             // 2
    detect_dtype<<<1, 1>>>(ei, N);                                 // 3
    gemm_tc<<<grid_l, 256, SM_TOTAL>>>(nullptr, nullptr, 0, N, 256, as1, ad1); // 4
    zero_counts<<<(N + 255) / 256, 256>>>(N);                      // 5
    hist_kernel<<<(E + 255) / 256, 256>>>(ei, E, N);               // 6
    alloc_rows<<<(N + 1023) / 1024, 1024>>>(N);                    // 7
    scatter_kernel<<<(E + 255) / 256, 256>>>(ei, E, N);            // 8
    gat_agg<<<N, 128>>>(g1, b1, m1, v1);                           // 9

    // --- layer 2 ---
    conv_split_w<<<(nw2 + 255) / 256, 256>>>(W2, nw2);
    gemm_tc<<<grid_l, 256, SM_TOTAL>>>(nullptr, nullptr, 0, N, 256, as2, ad2);
    gat_agg<<<N, 128>>>(g2, b2, m2, v2);

    // --- classifier ---
    conv_split_w<<<(nc2 + 255) / 256, 256>>>(Wc, nc2);
    gemm_tc<<<grid_l, 256, SM_TOTAL>>>(bc, out, 1, N, 64, nullptr, nullptr);
}

// round 13
// speedup vs baseline: 1.3802x; 1.3802x over previous
#include <cuda_runtime.h>
#include <cuda_bf16.h>
#include <cstdint>

// ---------------------------------------------------------------------------
// GATModel on GB300: tcgen05 bf16 split-GEMM — PERSISTENT CTAs over
// (128-row x 64-col) tiles, 4-stage K pipeline, double-buffered cp.async,
// next-tile loads overlapped with epilogue. + two-phase GAT aggregate.
// R13: revert R12's row-stripe (occ collapse); persistent R11 tiles instead.
// ---------------------------------------------------------------------------

#if defined(__CUDA_ARCH_FEAT_SM103_ALL) || defined(__CUDA_ARCH_FEAT_SM100_ALL) || \
    defined(__CUDA_ARCH_FEAT_SM101_ALL) || defined(__CUDA_ARCH_SPECIFIC__)
#define TC_OK 1
#else
#define TC_OK 0
#endif

#define NMAX 50000
#define EMAX 500000

__device__ float          g_buf1[NMAX * 256];
__device__ __nv_bfloat16  g_a_hi[NMAX * 256];
__device__ __nv_bfloat16  g_a_lo[NMAX * 256];
__device__ __nv_bfloat16  g_wb_hi[256 * 256];
__device__ __nv_bfloat16  g_wb_lo[256 * 256];
__device__ float g_ssrc[NMAX * 4];
__device__ float g_sdst[NMAX * 4];
__device__ int   g_counts[NMAX];
__device__ int   g_rowbeg[NMAX];
__device__ int   g_rowend[NMAX];
__device__ int   g_cursor[NMAX];
__device__ int   g_csrc[EMAX];
__device__ int   g_is64;
__device__ int   g_total;

// ---------------- edge_index dtype detection ----------------
__global__ void detect_dtype(const void* __restrict__ ei, int N) {
    const long long* p = (const long long*)ei;
    int ok = 1;
    for (int i = 0; i < 16; i++) {
        long long v = p[i];
        if (v < 0 || v >= (long long)N) ok = 0;
    }
    g_is64 = ok;
}
__device__ __forceinline__ int load_idx(const void* ei, long long pos) {
    if (g_is64) return (int)((const long long*)ei)[pos];
    return ((const int*)ei)[pos];
}

// ---------------- CSR build ----------------
__global__ void zero_counts(int N) {
    int i = blockIdx.x * blockDim.x + threadIdx.x;
    if (i < N) g_counts[i] = 0;
    if (i == 0) g_total = 0;
}
__global__ void hist_kernel(const void* __restrict__ ei, int E, int N) {
    int e = blockIdx.x * blockDim.x + threadIdx.x;
    if (e < E) {
        int d = load_idx(ei, (long long)E + e);
        if (d >= 0 && d < N) atomicAdd(&g_counts[d], 1);
    }
}
__global__ void __launch_bounds__(1024)
alloc_rows(int N) {
    __shared__ int sh[1024];
    __shared__ int sbase;
    int tid = threadIdx.x;
    int i = blockIdx.x * 1024 + tid;
    int c = (i < N) ? g_counts[i] : 0;
    sh[tid] = c;
    __syncthreads();
    for (int off = 1; off < 1024; off <<= 1) {
        int v = (tid >= off) ? sh[tid - off] : 0;
        __syncthreads();
        sh[tid] += v;
        __syncthreads();
    }
    if (tid == 1023) sbase = atomicAdd(&g_total, sh[1023]);
    __syncthreads();
    if (i < N) {
        int b = sbase + sh[tid] - c;
        g_rowbeg[i] = b;
        g_rowend[i] = b + c;
        g_cursor[i] = b;
    }
}
__global__ void scatter_kernel(const void* __restrict__ ei, int E, int N) {
    int e = blockIdx.x * blockDim.x + threadIdx.x;
    if (e < E) {
        int d = load_idx(ei, (long long)E + e);
        int s = load_idx(ei, e);
        if (d >= 0 && d < N && s >= 0 && s < N) {
            int pos = atomicAdd(&g_cursor[d], 1);
            if (pos >= 0 && pos < E) g_csrc[pos] = s;
        }
    }
}

// ---------------- fp32 -> bf16 hi/lo split conversions ----------------
__global__ void conv_split_x(const float* __restrict__ src, int n2) {
    int i = blockIdx.x * blockDim.x + threadIdx.x;
    if (i < n2) {
        float2 v = ((const float2*)src)[i];
        __nv_bfloat16 h0 = __float2bfloat16(v.x);
        __nv_bfloat16 h1 = __float2bfloat16(v.y);
        ((__nv_bfloat162*)g_a_hi)[i] = __halves2bfloat162(h0, h1);
        ((__nv_bfloat162*)g_a_lo)[i] = __halves2bfloat162(
            __float2bfloat16(v.x - __bfloat162float(h0)),
            __float2bfloat16(v.y - __bfloat162float(h1)));
    }
}
__global__ void conv_split_w(const float* __restrict__ src, int n2) {
    int i = blockIdx.x * blockDim.x + threadIdx.x;
    if (i < n2) {
        float2 v = ((const float2*)src)[i];
        __nv_bfloat16 h0 = __float2bfloat16(v.x);
        __nv_bfloat16 h1 = __float2bfloat16(v.y);
        ((__nv_bfloat162*)g_wb_hi)[i] = __halves2bfloat162(h0, h1);
        ((__nv_bfloat162*)g_wb_lo)[i] = __halves2bfloat162(
            __float2bfloat16(v.x - __bfloat162float(h0)),
            __float2bfloat16(v.y - __bfloat162float(h1)));
    }
}

// ---------------- tcgen05 helpers (arch-specific pass only) ----------------
#if TC_OK
__device__ __forceinline__ uint32_t elect_one_pred() {
    uint32_t pred;
    asm volatile("{\n\t.reg .pred p;\n\telect.sync _|p, 0xFFFFFFFF;\n\t"
                 "selp.b32 %0, 1, 0, p;\n\t}" : "=r"(pred));
    return pred;
}
__device__ __forceinline__ uint32_t smem_to_u32(const void* p) {
    uint32_t a;
    asm("{ .reg .u64 t; cvta.to.shared.u64 t, %1; cvt.u32.u64 %0, t; }"
        : "=r"(a) : "l"(p));
    return a;
}
#define MBARRIER_INIT(mbar, count) \
    asm volatile("mbarrier.init.shared.b64 [%0], %1;" \
                 :: "r"((uint32_t)(mbar)), "r"((uint32_t)(count)) : "memory")
#define MBARRIER_WAIT_PARITY(mbar, parity) do { \
    uint32_t _m = (uint32_t)(mbar), _p = (uint32_t)(parity), _d; \
    asm volatile("{\n\t.reg .pred p;\n\t" \
        "mbarrier.try_wait.parity.acquire.cta.shared::cta.b64 p, [%1], %2;\n\t" \
        "selp.b32 %0, 1, 0, p;\n\t}" : "=r"(_d) : "r"(_m), "r"(_p) : "memory"); \
    if (!_d) { \
        asm volatile("{\n\t.reg .pred P1;\n\t" \
            "WL_%=:\n\t" \
            "mbarrier.try_wait.parity.acquire.cta.shared::cta.b64 P1, [%0], %1, 0x989680;\n\t" \
            "@P1 bra.uni WD_%=;\n\tbra.uni WL_%=;\n\tWD_%=:\n\t}" \
            :: "r"(_m), "r"(_p) : "memory"); \
    } \
} while (0)
#define TCGEN05_ALLOC(sr, n) \
    asm volatile("tcgen05.alloc.cta_group::1.sync.aligned.shared::cta.b32 [%0], %1;" \
                 :: "r"((uint32_t)(sr)), "r"((uint32_t)(n)) : "memory")
#define TCGEN05_DEALLOC(t, n) \
    asm volatile("tcgen05.dealloc.cta_group::1.sync.aligned.b32 %0, %1;" \
                 :: "r"(t), "r"((uint32_t)(n)))
#define TCGEN05_RELINQ() \
    asm volatile("tcgen05.relinquish_alloc_permit.cta_group::1.sync.aligned;")
#define TCGEN05_COMMIT(mbar) \
    asm volatile("tcgen05.commit.cta_group::1.mbarrier::arrive::one.shared::cluster.b64 [%0];" \
                 :: "r"((uint32_t)(mbar)) : "memory")
#define TCGEN05_FENCE_AFTER() \
    asm volatile("tcgen05.fence::after_thread_sync;" ::: "memory")
#define TCGEN05_FENCE_BEFORE() \
    asm volatile("tcgen05.fence::before_thread_sync;" ::: "memory")
#define TCGEN05_WAIT_LD() \
    asm volatile("tcgen05.wait::ld.sync.aligned;" ::: "memory")
#define TCGEN05_LD_32X32B_X32(r, ta) \
    asm volatile("tcgen05.ld.sync.aligned.32x32b.x32.b32 " \
        "{%0, %1, %2, %3, %4, %5, %6, %7, %8, %9, %10, %11, %12, %13, %14, %15, " \
        " %16, %17, %18, %19, %20, %21, %22, %23, %24, %25, %26, %27, %28, %29, %30, %31}, [%32];" \
        : "=r"((r)[0]), "=r"((r)[1]), "=r"((r)[2]), "=r"((r)[3]), \
          "=r"((r)[4]), "=r"((r)[5]), "=r"((r)[6]), "=r"((r)[7]), \
          "=r"((r)[8]), "=r"((r)[9]), "=r"((r)[10]), "=r"((r)[11]), \
          "=r"((r)[12]), "=r"((r)[13]), "=r"((r)[14]), "=r"((r)[15]), \
          "=r"((r)[16]), "=r"((r)[17]), "=r"((r)[18]), "=r"((r)[19]), \
          "=r"((r)[20]), "=r"((r)[21]), "=r"((r)[22]), "=r"((r)[23]), \
          "=r"((r)[24]), "=r"((r)[25]), "=r"((r)[26]), "=r"((r)[27]), \
          "=r"((r)[28]), "=r"((r)[29]), "=r"((r)[30]), "=r"((r)[31]) \
        : "r"(ta))
#define CP_ASYNC16(dst, src) \
    asm volatile("cp.async.cg.shared.global [%0], [%1], 16;" \
                 :: "r"((uint32_t)(dst)), "l"(src) : "memory")
#define CP_COMMIT() \
    asm volatile("cp.async.commit_group;" ::: "memory")
#define CP_WAIT_GROUP(n) \
    asm volatile("cp.async.wait_group %0;" :: "n"(n) : "memory")

__device__ __forceinline__ uint64_t make_desc(uint32_t addr) {
    uint64_t base = (uint64_t(2) << 61) | (uint64_t(1) << 46) |
                    (uint64_t(64) << 32) | (uint64_t(1) << 16);
    return base | ((uint64_t)(addr >> 4) & 0x3FFF);
}
__device__ __forceinline__ void mma_f16_ss(uint32_t d, uint64_t ad, uint64_t bd,
                                           uint32_t idesc, bool en) {
    uint32_t e = en ? 1u : 0u;
    asm volatile("{\n\t.reg .pred p;\n\tsetp.ne.u32 p, %5, 0;\n\t"
                 "tcgen05.mma.cta_group::1.kind::f16 [%0], %1, %2, %3, {%4, %4, %4, %4}, p;\n\t}"
                 :: "r"(d), "l"(ad), "l"(bd), "r"(idesc), "r"(0u), "r"(e)
                 : "memory");
}
#define MMA_IDESC 0x8100490u
#endif  // TC_OK

// ---------------- persistent tcgen05 split-GEMM ----------------
// Tiles: C[128,64] each; 4 K-stages of 64, double-buffered 48K stage bufs.
// 296 persistent CTAs; next-tile stage0/1 loads overlap current epilogue.
#define SM_TMEM 0
#define SM_MB0 8
#define SM_MB1 16
#define SM_BUF 1024
#define STG_SZ 49152
#define OFF_ALO 16384
#define OFF_BHI 32768
#define OFF_BLO 40960
#define SM_TOTAL (1024 + 2 * STG_SZ)
#define GEMM_GRID 296

__global__ void __launch_bounds__(256)
gemm_tc(const float* __restrict__ bias,
        float* __restrict__ Cext, int toExt, int M, int Nout,
        const float* __restrict__ a_src, const float* __restrict__ a_dst) {
#if TC_OK
    extern __shared__ char smem[];
    uint32_t sb = smem_to_u32(smem);
    int tid = threadIdx.x;
    int wid = tid >> 5;
    int lane = tid & 31;
    float* C = toExt ? Cext : (float*)g_buf1;

    int nCB = Nout >> 6;
    int nRows = (M + 127) >> 7;
    int nTiles = nRows * nCB;

    if (wid == 0) {
        TCGEN05_ALLOC(sb + SM_TMEM, 128);
        TCGEN05_RELINQ();
    }
    if (tid == 0) {
        MBARRIER_INIT(sb + SM_MB0, 1);
        MBARRIER_INIT(sb + SM_MB1, 1);
    }
    __syncthreads();
    uint32_t tmem;
    asm volatile("ld.shared.b32 %0, [%1];" : "=r"(tmem) : "r"(sb + SM_TMEM));

    // constant per-thread layout pieces
    int ar = tid & 127;
    bool a_hi = tid < 128;
    int a_off_base = (ar >> 3) * 1024 + (ar & 7) * 128;
    int a_sub = a_hi ? 0 : OFF_ALO;
    const __nv_bfloat16* a_arr = a_hi ? g_a_hi : g_a_lo;

    int rb = tid >> 1;
    int br = rb & 63;
    bool b_hi = rb < 64;
    const __nv_bfloat16* b_arr = b_hi ? g_wb_hi : g_wb_lo;
    int b_off_base = (br >> 3) * 1024 + (br & 7) * 128;
    int b_sub = b_hi ? OFF_BHI : OFF_BLO;
    int b_c0 = (tid & 1) * 4;

    // loads stage s (0..3) of tile (row0, col0) into buffer s&1
    auto load_stage = [&](int row0, int col0, int s) {
        uint32_t bufb = sb + SM_BUF + (s & 1) * STG_SZ;
        {
            const uint4* src = (const uint4*)(a_arr + (size_t)(row0 + ar) * 256 + s * 64);
            bool ok = (row0 + ar) < M;
#pragma unroll
            for (int c = 0; c < 8; c++) {
                int off = a_off_base + c * 16;
                off ^= (off >> 3) & 0x70;
                if (ok) CP_ASYNC16(bufb + a_sub + off, src + c);
                else *(uint4*)(smem + (bufb - sb) + a_sub + off) =
                         make_uint4(0u, 0u, 0u, 0u);
            }
        }
        {
            const uint4* src = (const uint4*)(b_arr + (size_t)(col0 + br) * 256 + s * 64);
#pragma unroll
            for (int q = 0; q < 4; q++) {
                int c = b_c0 + q;
                int off = b_off_base + c * 16;
                off ^= (off >> 3) & 0x70;
                CP_ASYNC16(bufb + b_sub + off, src + c);
            }
        }
        CP_COMMIT();
    };

    int t = blockIdx.x;
    if (t < nTiles) {
        int row0 = (t / nCB) * 128, col0 = (t % nCB) * 64;
        load_stage(row0, col0, 0);
        load_stage(row0, col0, 1);
    }

    for (; t < nTiles; t += GEMM_GRID) {
        int row0 = (t / nCB) * 128;
        int col0 = (t % nCB) * 64;
        int tn = t + GEMM_GRID;
        int nrow0 = (tn < nTiles) ? (tn / nCB) * 128 : 0;
        int ncol0 = (tn < nTiles) ? (tn % nCB) * 64 : 0;

#pragma unroll
        for (int s = 0; s < 4; s++) {
            if (s < 3) CP_WAIT_GROUP(1); else CP_WAIT_GROUP(0);
            __syncthreads();
            asm volatile("fence.proxy.async.shared::cta;" ::: "memory");

            if (wid == 0) {
                if (elect_one_pred()) {
                    uint32_t bufb = sb + SM_BUF + (s & 1) * STG_SZ;
                    uint64_t dA_hi = make_desc(bufb);
                    uint64_t dA_lo = make_desc(bufb + OFF_ALO);
                    uint64_t dB_hi = make_desc(bufb + OFF_BHI);
                    uint64_t dB_lo = make_desc(bufb + OFF_BLO);
#pragma unroll
                    for (int term = 0; term < 3; term++) {
                        uint64_t da = (term == 2) ? dA_lo : dA_hi;
                        uint64_t db = (term == 1) ? dB_lo : dB_hi;
#pragma unroll
                        for (int kc = 0; kc < 4; kc++) {
                            mma_f16_ss(tmem, da + kc * 2, db + kc * 2, MMA_IDESC,
                                       !(s == 0 && term == 0 && kc == 0));
                        }
                    }
                    TCGEN05_COMMIT(sb + ((s & 1) ? SM_MB1 : SM_MB0));
                }
            }
            if (s < 2) {
                MBARRIER_WAIT_PARITY(sb + ((s & 1) ? SM_MB1 : SM_MB0), 0);
                load_stage(row0, col0, s + 2);
            }
        }

        MBARRIER_WAIT_PARITY(sb + SM_MB0, 1);
        MBARRIER_WAIT_PARITY(sb + SM_MB1, 1);
        TCGEN05_FENCE_AFTER();

        // overlap: issue next tile's stage 0/1 loads before the epilogue
        if (tn < nTiles) {
            load_stage(nrow0, ncol0, 0);
            load_stage(nrow0, ncol0, 1);
        }

        // ---- epilogue ----
        if (wid < 4) {
            uint32_t d0[32], d1[32];
            TCGEN05_LD_32X32B_X32(d0, tmem);
            TCGEN05_LD_32X32B_X32(d1, tmem + 32);
            TCGEN05_WAIT_LD();
            int r = row0 + wid * 32 + lane;
            if (r < M) {
                float cv[64];
#pragma unroll
                for (int j = 0; j < 32; j++) {
                    cv[j] = __uint_as_float(d0[j]);
                    cv[32 + j] = __uint_as_float(d1[j]);
                }
                if (bias) {
#pragma unroll
                    for (int j = 0; j < 64; j++) cv[j] += bias[col0 + j];
                }
                float* crow = C + (size_t)r * Nout + col0;
#pragma unroll
                for (int q = 0; q < 16; q++) {
                    *(float4*)(crow + q * 4) = make_float4(
                        cv[4 * q], cv[4 * q + 1], cv[4 * q + 2], cv[4 * q + 3]);
                }
                if (a_src) {
                    int head = col0 >> 6;
                    float vs = 0.f, vd = 0.f;
#pragma unroll
                    for (int j = 0; j < 64; j++) {
                        vs = fmaf(cv[j], a_src[col0 + j], vs);
                        vd = fmaf(cv[j], a_dst[col0 + j], vd);
                    }
                    g_ssrc[r * 4 + head] = vs;
                    g_sdst[r * 4 + head] = vd;
                }
            }
            TCGEN05_FENCE_BEFORE();
        }
        __syncthreads();   // all LDTMs done before next tile's MMA reuses TMEM
    }

    __syncthreads();
    if (tid == 0) {
        asm volatile("mbarrier.inval.shared.b64 [%0];" :: "r"(sb + SM_MB0) : "memory");
        asm volatile("mbarrier.inval.shared.b64 [%0];" :: "r"(sb + SM_MB1) : "memory");
    }
    if (wid == 0) TCGEN05_DEALLOC(tmem, 128);
#endif  // TC_OK
}

// ---------------- GAT aggregate + BN + ELU (chunked two-phase) ----------------
__global__ void __launch_bounds__(128)
gat_agg(const float* __restrict__ gamma, const float* __restrict__ beta,
        const float* __restrict__ mean, const float* __restrict__ var) {
    __shared__ float wgt[32][4];
    __shared__ int   sidx[32];
    __shared__ float smax[4];

    int n = blockIdx.x;
    int tid = threadIdx.x;
    int head = tid >> 5;
    int lane = tid & 31;
    int beg = g_rowbeg[n];
    int end = g_rowend[n];
    const float* hfeat = g_buf1;

    {
        float sd_h = g_sdst[n * 4 + head];
        float m = 0.f;
        for (int i = beg + lane; i < end; i += 32) {
            int s = g_csrc[i];
            float e = g_ssrc[s * 4 + head] + sd_h;
            e = (e >= 0.f) ? e : 0.2f * e;
            m = fmaxf(m, e);
        }
#pragma unroll
        for (int o = 16; o; o >>= 1) m = fmaxf(m, __shfl_xor_sync(~0u, m, o));
        if (lane == 0) smax[head] = m;
    }
    __syncthreads();

    int eh = tid & 3;
    int eo = tid >> 2;
    float sd_eh = g_sdst[n * 4 + eh];
    float m_eh = smax[eh];

    float acc0 = 0.f, acc1 = 0.f, ws = 0.f;
    int c = tid * 2;

    for (int base = beg; base < end; base += 32) {
        int cnt = min(32, end - base);
        {
            float w = 0.f;
            int s = -1;
            if (eo < cnt) {
                s = g_csrc[base + eo];
                float e = g_ssrc[s * 4 + eh] + sd_eh;
                e = (e >= 0.f) ? e : 0.2f * e;
                w = __expf(e - m_eh);
            }
            wgt[eo][eh] = w;
            if (eh == 0) sidx[eo] = s;
        }
        __syncthreads();
        for (int j = 0; j < cnt; j++) {
            float w = wgt[j][head];
            ws += w;
            float2 hv = *(const float2*)&hfeat[(size_t)sidx[j] * 256 + c];
            acc0 = fmaf(w, hv.x, acc0);
            acc1 = fmaf(w, hv.y, acc1);
        }
        __syncthreads();
    }

    float inv = 1.f / fmaxf(ws, 1e-9f);
    float o0 = acc0 * inv;
    float o1 = acc1 * inv;

    o0 = (o0 - mean[c]) * rsqrtf(var[c] + 1e-5f) * gamma[c] + beta[c];
    o1 = (o1 - mean[c + 1]) * rsqrtf(var[c + 1] + 1e-5f) * gamma[c + 1] + beta[c + 1];
    o0 = (o0 > 0.f) ? o0 : expm1f(o0);
    o1 = (o1 > 0.f) ? o1 : expm1f(o1);

    __nv_bfloat16 h0 = __float2bfloat16(o0);
    __nv_bfloat16 h1 = __float2bfloat16(o1);
    size_t idx2 = ((size_t)n * 256 + c) >> 1;
    ((__nv_bfloat162*)g_a_hi)[idx2] = __halves2bfloat162(h0, h1);
    ((__nv_bfloat162*)g_a_lo)[idx2] = __halves2bfloat162(
        __float2bfloat16(o0 - __bfloat162float(h0)),
        __float2bfloat16(o1 - __bfloat162float(h1)));
}

// ---------------------------------------------------------------------------
extern "C" void kernel_launch(void* const* d_in, const int* in_sizes, int n_in,
                              void* d_out, int out_size) {
    const float* x   = (const float*)d_in[0];
    const void*  ei  = d_in[1];
    const float* W1  = (const float*)d_in[2];
    const float* as1 = (const float*)d_in[3];
    const float* ad1 = (const float*)d_in[4];
    const float* g1  = (const float*)d_in[5];
    const float* b1  = (const float*)d_in[6];
    const float* m1  = (const float*)d_in[7];
    const float* v1  = (const float*)d_in[8];
    const float* W2  = (const float*)d_in[9];
    const float* as2 = (const float*)d_in[10];
    const float* ad2 = (const float*)d_in[11];
    const float* g2  = (const float*)d_in[12];
    const float* b2  = (const float*)d_in[13];
    const float* m2  = (const float*)d_in[14];
    const float* v2  = (const float*)d_in[15];
    const float* Wc  = (const float*)d_in[16];
    const float* bc  = (const float*)d_in[17];
    float* out = (float*)d_out;

    int N = in_sizes[0] / 256;
    int E = in_sizes[1] / 2;

    cudaFuncSetAttribute(gemm_tc, cudaFuncAttributeMaxDynamicSharedMemorySize,
                         SM_TOTAL);

    int nx2 = N * 128;
    int nw2 = 256 * 256 / 2;
    int nc2 = 64 * 256 / 2;

    // gemm_tc stays the 4th launch for ncu.
    conv_split_x<<<(nx2 + 255) / 256, 256>>>(x, nx2);              // 1
    conv_split_w<<<(nw2 + 255) / 256, 256>>>(W1, nw2);             // 2
    detect_dtype<<<1, 1>>>(ei, N);                                 // 3
    gemm_tc<<<GEMM_GRID, 256, SM_TOTAL>>>(nullptr, nullptr, 0, N, 256, as1, ad1); // 4
    zero_counts<<<(N + 255) / 256, 256>>>(N);                      // 5
    hist_kernel<<<(E + 255) / 256, 256>>>(ei, E, N);               // 6
    alloc_rows<<<(N + 1023) / 1024, 1024>>>(N);                    // 7
    scatter_kernel<<<(E + 255) / 256, 256>>>(ei, E, N);            // 8
    gat_agg<<<N, 128>>>(g1, b1, m1, v1);                           // 9

    // --- layer 2 ---
    conv_split_w<<<(nw2 + 255) / 256, 256>>>(W2, nw2);
    gemm_tc<<<GEMM_GRID, 256, SM_TOTAL>>>(nullptr, nullptr, 0, N, 256, as2, ad2);
    gat_agg<<<N, 128>>>(g2, b2, m2, v2);

    // --- classifier ---
    conv_split_w<<<(nc2 + 255) / 256, 256>>>(Wc, nc2);
    gemm_tc<<<GEMM_GRID, 256, SM_TOTAL>>>(bc, out, 1, N, 64, nullptr, nullptr);
}